// round 11
// baseline (speedup 1.0000x reference)
#include <cuda_runtime.h>
#include <cuda_bf16.h>
#include <math.h>
#include <stdint.h>

// Problem constants
#define Hdim   3584
#define Bb     8
#define NH     28
#define KVH    4
#define GS     7
#define HD     128
#define MB     16
#define BSZ    256
#define Rr     32          // B*KVH
#define QKVROWS 4608       // 3584 q + 512 k + 512 v
#define SCALE  0.08838834764831845f
#define NEG_INF (-1e30f)
#define NSPLIT 7           // column splits (3584 / 512)

#define GEMV_SMEM (4 * 1024 * 16)   // 4 stages x 1024 float4 = 64 KB

// -------- scratch (device globals, no allocation) --------
__device__ float g_qkvp[NSPLIT * Bb * QKVROWS]; // qkv partials [y][b][vrow]
__device__ float g_part[Rr * MB * GS * HD];     // per-chunk partial PV sums
__device__ float g_ml[Rr * MB * GS * 2];        // per-chunk (m, l)
__device__ float g_attn[Bb * Hdim];             // attention output pre O-proj

// ---- cp.async helpers ----
#define CPA16(dst_u32, src_ptr) \
    asm volatile("cp.async.cg.shared.global [%0], [%1], 16;" :: "r"(dst_u32), "l"(src_ptr))
#define CP_COMMIT() asm volatile("cp.async.commit_group;")
#define CP_WAIT(N)  asm volatile("cp.async.wait_group %0;" :: "n"(N))

// ============================================================
// GEMV core: block = 256 thr = 8 warps, 32 rows x 512-col slice.
// Weights streamed via cp.async into a 4-stage smem ring (all
// stages in flight up-front -> no register-scoreboard MLP limit).
// Warp computes 4 rows x 8 batches from smem weights + L1 x.
// ============================================================
__device__ __forceinline__ void gemv_cp(const float* __restrict__ Wrow0, // row 0 of this block
                                        const float4* __restrict__ x4,
                                        int y, int t, float acc[4][8],
                                        float4* wsm) {
    const uint32_t smbase = (uint32_t)__cvta_generic_to_shared(wsm);
    const int row = t >> 3;         // 0..31
    const int seg = t & 7;          // 0..7
    const float* src_row = Wrow0 + (size_t)row * Hdim + y * 512;

    // issue all 4 stages (each: 32 rows x 128 cols = 16 KB)
#pragma unroll
    for (int s = 0; s < 4; s++) {
#pragma unroll
        for (int cc = 0; cc < 4; cc++) {
            const int chunk = seg + cc * 8;   // 0..31 (float4 within stage-row)
            const uint32_t dst = smbase + (uint32_t)((s * 1024 + row * 32 + chunk) << 4);
            CPA16(dst, src_row + s * 128 + chunk * 4);
        }
        CP_COMMIT();
    }

    const int lane = t & 31;
    const int warp = t >> 5;

#define GEMV_STAGE(S, NWAIT)                                                    \
    {                                                                           \
        CP_WAIT(NWAIT);                                                         \
        __syncthreads();                                                        \
        const float4* wr = wsm + (S) * 1024 + (warp * 4) * 32 + lane;           \
        const float4 w0 = wr[0];                                                \
        const float4 w1 = wr[32];                                               \
        const float4 w2 = wr[64];                                               \
        const float4 w3 = wr[96];                                               \
        const int c4 = y * 128 + (S) * 32 + lane;                               \
        _Pragma("unroll")                                                       \
        for (int b = 0; b < 8; b++) {                                           \
            const float4 xv = x4[b * 896 + c4];                                 \
            acc[0][b] += w0.x * xv.x + w0.y * xv.y + w0.z * xv.z + w0.w * xv.w; \
            acc[1][b] += w1.x * xv.x + w1.y * xv.y + w1.z * xv.z + w1.w * xv.w; \
            acc[2][b] += w2.x * xv.x + w2.y * xv.y + w2.z * xv.z + w2.w * xv.w; \
            acc[3][b] += w3.x * xv.x + w3.y * xv.y + w3.z * xv.z + w3.w * xv.w; \
        }                                                                       \
    }

    GEMV_STAGE(0, 3)
    GEMV_STAGE(1, 2)
    GEMV_STAGE(2, 1)
    GEMV_STAGE(3, 0)
#undef GEMV_STAGE

#pragma unroll
    for (int r = 0; r < 4; r++)
#pragma unroll
        for (int b = 0; b < 8; b++) {
#pragma unroll
            for (int off = 16; off; off >>= 1)
                acc[r][b] += __shfl_xor_sync(0xffffffffu, acc[r][b], off);
        }
}

// Fused QKV projection. grid (144, 7), 256 threads, 64 KB dyn smem.
__global__ __launch_bounds__(256, 2) void qkv_gemv(
    const float* __restrict__ hid,
    const float* __restrict__ q_w, const float* __restrict__ q_b,
    const float* __restrict__ k_w, const float* __restrict__ k_b,
    const float* __restrict__ v_w, const float* __restrict__ v_b) {
    extern __shared__ float4 wsm[];
    const int t = threadIdx.x;
    const int lane = t & 31;
    const int warp = t >> 5;
    const int y = blockIdx.y;
    const int rbase = blockIdx.x * 32;               // virtual row base (block)

    const float* W; const float* bias; int wrow;
    if (rbase < 3584)      { W = q_w; bias = q_b; wrow = rbase; }
    else if (rbase < 4096) { W = k_w; bias = k_b; wrow = rbase - 3584; }
    else                   { W = v_w; bias = v_b; wrow = rbase - 4096; }

    float acc[4][8];
#pragma unroll
    for (int r = 0; r < 4; r++)
#pragma unroll
        for (int b = 0; b < 8; b++) acc[r][b] = 0.f;

    gemv_cp(W + (size_t)wrow * Hdim, (const float4*)hid, y, t, acc, wsm);

    if (lane == 0) {
        const int r0 = wrow + warp * 4;
        const int vr0 = rbase + warp * 4;
#pragma unroll
        for (int r = 0; r < 4; r++) {
            const float bv = (y == 0) ? bias[r0 + r] : 0.f;
#pragma unroll
            for (int b = 0; b < 8; b++)
                g_qkvp[(size_t)(y * 8 + b) * QKVROWS + vr0 + r] = acc[r][b] + bv;
        }
    }
}

// O projection. grid (112, 7), 256 threads, 64 KB dyn smem.
// Atomic accumulate into out (zeroed earlier by attn_combine).
__global__ __launch_bounds__(256, 2) void o_gemv(const float* __restrict__ o_w,
                                                 float* __restrict__ out) {
    extern __shared__ float4 wsm[];
    const int t = threadIdx.x;
    const int lane = t & 31;
    const int warp = t >> 5;
    const int y = blockIdx.y;
    const int rbase = blockIdx.x * 32;

    float acc[4][8];
#pragma unroll
    for (int r = 0; r < 4; r++)
#pragma unroll
        for (int b = 0; b < 8; b++) acc[r][b] = 0.f;

    gemv_cp(o_w + (size_t)rbase * Hdim, (const float4*)g_attn, y, t, acc, wsm);

    if (lane == 0) {
        const int r0 = rbase + warp * 4;
#pragma unroll
        for (int r = 0; r < 4; r++)
#pragma unroll
            for (int b = 0; b < 8; b++)
                atomicAdd(&out[(size_t)b * Hdim + r0 + r], acc[r][b]);
    }
}

// helper: sum qkv partials for (batch b, virtual row vr)
__device__ __forceinline__ float qkv_sum(int b, int vr) {
    float s = 0.f;
#pragma unroll
    for (int yy = 0; yy < NSPLIT; yy++)
        s += g_qkvp[(size_t)(yy * 8 + b) * QKVROWS + vr];
    return s;
}

// ============================================================
// Attention partial (flash-decode split-K) with fused RoPE.
// grid = (16 chunks, 32 rows), 256 threads, dynamic smem.
// ============================================================
#define KROW 129
#define SMEM_ATTN ((16512 + 896 + 1792 + 128 + 128 + 896) * 4)

__global__ __launch_bounds__(256, 2) void attn_partial(
        const float* __restrict__ k_pool,
        const float* __restrict__ v_pool,
        const int* __restrict__ block_table,
        const int* __restrict__ cache_seqlens,
        const float* __restrict__ cos_,
        const float* __restrict__ sin_) {
    const int c = blockIdx.x;
    const int r = blockIdx.y;
    const int seqlen = cache_seqlens[r];
    const int base = c * BSZ;
    if (base >= seqlen) return;

    extern __shared__ float sm[];
    float* ks     = sm;               // [128][129] staged K half-chunk
    float* q_s    = sm + 16512;       // [7][128] rope'd q
    float* p_s    = q_s + 896;        // [7][256]
    float* knew_s = p_s + 1792;       // [128]
    float* vnew_s = knew_s + 128;     // [128]
    float* acc2_s = vnew_s + 128;     // [7][128]

    const int nvalid = min(BSZ, seqlen - base);
    const int pos = seqlen - 1;
    const int jpos = pos - base;
    const int b = r >> 2;
    const int kvh = r & 3;
    const int blk = block_table[r * MB + c];
    const float* __restrict__ K = k_pool + (size_t)blk * BSZ * HD;
    const float* __restrict__ V = v_pool + (size_t)blk * BSZ * HD;

    const int t = threadIdx.x;
    const float* cb = cos_ + b * HD;
    const float* sb = sin_ + b * HD;

    // ---- build q (7 heads, rope), k_new (rope), v_new from qkv partials ----
    {
        const int qvbase = kvh * GS * HD;
        for (int i = t; i < GS * 64; i += 256) {
            const int g = i >> 6;
            const int d = i & 63;
            const float cc = cb[d], ss = sb[d];
            const float a  = qkv_sum(b, qvbase + g * HD + d);
            const float b2 = qkv_sum(b, qvbase + g * HD + d + 64);
            q_s[g * HD + d]      = a * cc - b2 * ss;
            q_s[g * HD + d + 64] = b2 * cc + a * ss;
        }
        if (t < 64) {   // k_new rope pairs
            const int vr = 3584 + kvh * HD + t;
            const float cc = cb[t], ss = sb[t];
            const float a  = qkv_sum(b, vr);
            const float b2 = qkv_sum(b, vr + 64);
            knew_s[t]      = a * cc - b2 * ss;
            knew_s[t + 64] = b2 * cc + a * ss;
        } else if (t < 192) {  // v_new plain
            const int d = t - 64;
            vnew_s[d] = qkv_sum(b, 4096 + kvh * HD + d);
        }
    }

    // ---- phase 1: QK scores via staged smem halves ----
    const int jl = t & 127;
    const int hh = t >> 7;
    const bool valid_tok = (t < nvalid);
    float sc[GS];
#pragma unroll
    for (int g = 0; g < GS; g++) sc[g] = 0.f;

    for (int h = 0; h < 2; h++) {
        const int hbase = h * 128;
        if (hbase >= nvalid) break;
        __syncthreads();   // prev-half compute done / q+knew ready
        // stage 128 rows, coalesced; substitute rope'd new-token row inline
        const int jloc = jpos - hbase;       // in [0,128) iff new token in this half
        const float* Ksrc = K + (size_t)hbase * HD;
#pragma unroll 8
        for (int ii = 0; ii < 64; ii++) {
            const int w_idx = t + ii * 256;
            const int row = w_idx >> 7;
            const int col = w_idx & 127;
            float val = Ksrc[w_idx];
            if (row == jloc) val = knew_s[col];
            ks[row * KROW + col] = val;
        }
        __syncthreads();
        if (hh == h && valid_tok) {
            const float* krow = ks + jl * KROW;
            const float4* q4 = (const float4*)q_s;
#pragma unroll 4
            for (int u = 0; u < 32; u++) {
                const float k0 = krow[4 * u + 0];
                const float k1 = krow[4 * u + 1];
                const float k2 = krow[4 * u + 2];
                const float k3 = krow[4 * u + 3];
#pragma unroll
                for (int g = 0; g < GS; g++) {
                    const float4 qv = q4[g * 32 + u];
                    sc[g] += k0 * qv.x + k1 * qv.y + k2 * qv.z + k3 * qv.w;
                }
            }
        }
    }

    // ---- phase 2: softmax, warp per head ----
#pragma unroll
    for (int g = 0; g < GS; g++)
        p_s[g * 256 + t] = valid_tok ? sc[g] * SCALE : NEG_INF;
    __syncthreads();

    const int lane = t & 31, warp = t >> 5;
    const int rc = r * MB + c;
    if (warp < GS) {
        const int g = warp;
        float v[8];
#pragma unroll
        for (int i = 0; i < 8; i++) v[i] = p_s[g * 256 + lane + i * 32];
        float m = v[0];
#pragma unroll
        for (int i = 1; i < 8; i++) m = fmaxf(m, v[i]);
#pragma unroll
        for (int off = 16; off; off >>= 1)
            m = fmaxf(m, __shfl_xor_sync(0xffffffffu, m, off));
        float l = 0.f;
#pragma unroll
        for (int i = 0; i < 8; i++) {
            const float e = __expf(v[i] - m);
            p_s[g * 256 + lane + i * 32] = e;
            l += e;
        }
#pragma unroll
        for (int off = 16; off; off >>= 1)
            l += __shfl_xor_sync(0xffffffffu, l, off);
        if (lane == 0) {
            g_ml[rc * (GS * 2) + g * 2 + 0] = m;
            g_ml[rc * (GS * 2) + g * 2 + 1] = l;
        }
    }
    __syncthreads();

    // ---- phase 3: PV, thread = dim, tokens split across halves.
    const int d = t & 127;
    const int half = t >> 7;
    const int j0 = half * 128;
    float acc[GS];
#pragma unroll
    for (int g = 0; g < GS; g++) acc[g] = 0.f;
    const int jend = min(128, nvalid - j0);
    if (jend > 0) {
        const int jend4 = (jend + 3) & ~3;
        for (int jj = 0; jj < jend4; jj += 4) {
            const int jt = j0 + jj;
            const float vv0 = (jt + 0 == jpos) ? vnew_s[d] : V[(size_t)(jt + 0) * HD + d];
            const float vv1 = (jt + 1 == jpos) ? vnew_s[d] : V[(size_t)(jt + 1) * HD + d];
            const float vv2 = (jt + 2 == jpos) ? vnew_s[d] : V[(size_t)(jt + 2) * HD + d];
            const float vv3 = (jt + 3 == jpos) ? vnew_s[d] : V[(size_t)(jt + 3) * HD + d];
            float4 p4[GS];
#pragma unroll
            for (int g = 0; g < GS; g++)
                p4[g] = *(const float4*)(p_s + g * 256 + jt);
#pragma unroll
            for (int g = 0; g < GS; g++)
                acc[g] += p4[g].x * vv0 + p4[g].y * vv1 + p4[g].z * vv2 + p4[g].w * vv3;
        }
    }
    if (half == 1) {
#pragma unroll
        for (int g = 0; g < GS; g++) acc2_s[g * 128 + d] = acc[g];
    }
    __syncthreads();
    if (half == 0) {
        float* outp = g_part + (size_t)rc * (GS * HD);
#pragma unroll
        for (int g = 0; g < GS; g++)
            outp[g * HD + d] = acc[g] + acc2_s[g * 128 + d];
    }
}

// ============================================================
// Combine split-K partials + zero final out for o_gemv atomics.
// grid = (GS, Rr), 128 threads.  224*128 == 28672 == out size.
// ============================================================
__global__ void attn_combine(const int* __restrict__ cache_seqlens,
                             float* __restrict__ out) {
    const int g = blockIdx.x;
    const int r = blockIdx.y;
    const int d = threadIdx.x;

    out[(blockIdx.y * GS + blockIdx.x) * 128 + d] = 0.f;

    const int seqlen = cache_seqlens[r];
    const int nc = (seqlen + BSZ - 1) >> 8;

    float M = NEG_INF;
    for (int c = 0; c < nc; c++)
        M = fmaxf(M, g_ml[(r * MB + c) * (GS * 2) + g * 2]);
    float L = 0.f, acc = 0.f;
    for (int c = 0; c < nc; c++) {
        const int rc = r * MB + c;
        const float m = g_ml[rc * (GS * 2) + g * 2 + 0];
        const float l = g_ml[rc * (GS * 2) + g * 2 + 1];
        const float w = __expf(m - M);
        L += l * w;
        acc += w * g_part[(size_t)rc * (GS * HD) + g * HD + d];
    }
    const int b = r >> 2, kvh = r & 3;
    g_attn[(size_t)b * Hdim + (kvh * GS + g) * HD + d] = acc / L;
}

// ============================================================
extern "C" void kernel_launch(void* const* d_in, const int* in_sizes, int n_in,
                              void* d_out, int out_size) {
    const float* hid  = (const float*)d_in[0];
    const float* cosw = (const float*)d_in[1];
    const float* sinw = (const float*)d_in[2];
    const float* q_w  = (const float*)d_in[3];
    const float* q_b  = (const float*)d_in[4];
    const float* k_w  = (const float*)d_in[5];
    const float* k_b  = (const float*)d_in[6];
    const float* v_w  = (const float*)d_in[7];
    const float* v_b  = (const float*)d_in[8];
    const float* o_w  = (const float*)d_in[9];
    const float* k_pool = (const float*)d_in[10];
    const float* v_pool = (const float*)d_in[11];
    const int* block_table   = (const int*)d_in[12];
    const int* cache_seqlens = (const int*)d_in[13];
    float* out = (float*)d_out;

    cudaFuncSetAttribute(attn_partial, cudaFuncAttributeMaxDynamicSharedMemorySize, SMEM_ATTN);
    cudaFuncSetAttribute(qkv_gemv, cudaFuncAttributeMaxDynamicSharedMemorySize, GEMV_SMEM);
    cudaFuncSetAttribute(o_gemv,  cudaFuncAttributeMaxDynamicSharedMemorySize, GEMV_SMEM);

    // Fused QKV projections: 4608 rows / 32 per block, 7 col-slices
    qkv_gemv<<<dim3(144, NSPLIT), 256, GEMV_SMEM>>>(hid, q_w, q_b, k_w, k_b, v_w, v_b);
    // flash-decode partials (rope + qkv-partial reduce fused inside)
    attn_partial<<<dim3(MB, Rr), 256, SMEM_ATTN>>>(k_pool, v_pool, block_table,
                                                   cache_seqlens, cosw, sinw);
    // combine + zero out
    attn_combine<<<dim3(GS, Rr), 128>>>(cache_seqlens, out);
    // O projection: 3584 rows / 32 per block, 7 col-slices, atomic accumulate
    o_gemv<<<dim3(112, NSPLIT), 256, GEMV_SMEM>>>(o_w, out);
}

// round 12
// speedup vs baseline: 1.3356x; 1.3356x over previous
#include <cuda_runtime.h>
#include <cuda_bf16.h>
#include <math.h>
#include <stdint.h>

// Problem constants
#define Hdim   3584
#define Bb     8
#define NH     28
#define KVH    4
#define GS     7
#define HD     128
#define MB     16
#define BSZ    256
#define Rr     32          // B*KVH
#define QKVROWS 4608       // 3584 q + 512 k + 512 v
#define SCALE  0.08838834764831845f
#define NEG_INF (-1e30f)
#define NSPLIT 7           // column splits (3584 / 512)

// -------- scratch (device globals, no allocation) --------
__device__ float g_qkvp[NSPLIT * Bb * QKVROWS]; // qkv partials [y][b][vrow]
__device__ float g_part[Rr * MB * GS * HD];     // per-chunk partial PV sums
__device__ float g_ml[Rr * MB * GS * 2];        // per-chunk (m, l)
__device__ float g_attn[Bb * Hdim];             // attention output pre O-proj

// ---- cp.async helpers ----
#define CPA16(dst_u32, src_ptr) \
    asm volatile("cp.async.cg.shared.global [%0], [%1], 16;" :: "r"(dst_u32), "l"(src_ptr))
#define CP_COMMIT() asm volatile("cp.async.commit_group;")
#define CP_WAIT0()  asm volatile("cp.async.wait_group 0;")

// ============================================================
// GEMV core (R9-proven best): warp = 4 rows x 512-col slice,
// 8 batches, double-buffered weight prefetch @ 128-reg budget.
// ============================================================
__device__ __forceinline__ void gemv4x8_pipe(const float4* __restrict__ x4,
                                             const float4* __restrict__ w40,
                                             const float4* __restrict__ w41,
                                             const float4* __restrict__ w42,
                                             const float4* __restrict__ w43,
                                             int y, int lane, float acc[4][8]) {
    const int cb = y * 128 + lane;
    float4 wc0 = w40[cb];
    float4 wc1 = w41[cb];
    float4 wc2 = w42[cb];
    float4 wc3 = w43[cb];

#pragma unroll
    for (int u = 0; u < 4; u++) {
        float4 wn0, wn1, wn2, wn3;
        if (u < 3) {
            const int cn = cb + (u + 1) * 32;
            wn0 = w40[cn];
            wn1 = w41[cn];
            wn2 = w42[cn];
            wn3 = w43[cn];
        }
        const int c4 = cb + u * 32;
#pragma unroll
        for (int b = 0; b < 8; b++) {
            const float4 xv = x4[b * 896 + c4];
            acc[0][b] += wc0.x * xv.x + wc0.y * xv.y + wc0.z * xv.z + wc0.w * xv.w;
            acc[1][b] += wc1.x * xv.x + wc1.y * xv.y + wc1.z * xv.z + wc1.w * xv.w;
            acc[2][b] += wc2.x * xv.x + wc2.y * xv.y + wc2.z * xv.z + wc2.w * xv.w;
            acc[3][b] += wc3.x * xv.x + wc3.y * xv.y + wc3.z * xv.z + wc3.w * xv.w;
        }
        if (u < 3) { wc0 = wn0; wc1 = wn1; wc2 = wn2; wc3 = wn3; }
    }

#pragma unroll
    for (int r = 0; r < 4; r++)
#pragma unroll
        for (int b = 0; b < 8; b++) {
#pragma unroll
            for (int off = 16; off; off >>= 1)
                acc[r][b] += __shfl_xor_sync(0xffffffffu, acc[r][b], off);
        }
}

// Fused QKV projection. grid (144, 7), 256 threads.
__global__ __launch_bounds__(256, 2) void qkv_gemv(
    const float* __restrict__ hid,
    const float* __restrict__ q_w, const float* __restrict__ q_b,
    const float* __restrict__ k_w, const float* __restrict__ k_b,
    const float* __restrict__ v_w, const float* __restrict__ v_b) {
    const int t = threadIdx.x;
    const int lane = t & 31;
    const int warp = t >> 5;
    const int y = blockIdx.y;
    const int rbase = blockIdx.x * 32 + warp * 4;   // virtual row base

    const float* W; const float* bias; int wrow;
    if (rbase < 3584)      { W = q_w; bias = q_b; wrow = rbase; }
    else if (rbase < 4096) { W = k_w; bias = k_b; wrow = rbase - 3584; }
    else                   { W = v_w; bias = v_b; wrow = rbase - 4096; }

    const float4* w40 = (const float4*)(W + (size_t)(wrow + 0) * Hdim);
    const float4* w41 = (const float4*)(W + (size_t)(wrow + 1) * Hdim);
    const float4* w42 = (const float4*)(W + (size_t)(wrow + 2) * Hdim);
    const float4* w43 = (const float4*)(W + (size_t)(wrow + 3) * Hdim);

    float acc[4][8];
#pragma unroll
    for (int r = 0; r < 4; r++)
#pragma unroll
        for (int b = 0; b < 8; b++) acc[r][b] = 0.f;

    gemv4x8_pipe((const float4*)hid, w40, w41, w42, w43, y, lane, acc);

    if (lane == 0) {
#pragma unroll
        for (int r = 0; r < 4; r++) {
            const float bv = (y == 0) ? bias[wrow + r] : 0.f;
#pragma unroll
            for (int b = 0; b < 8; b++)
                g_qkvp[(size_t)(y * 8 + b) * QKVROWS + rbase + r] = acc[r][b] + bv;
        }
    }
}

// O projection. grid (112, 7), 256 threads.
// Atomic accumulate into out (zeroed earlier by attn_combine).
__global__ __launch_bounds__(256, 2) void o_gemv(const float* __restrict__ o_w,
                                                 float* __restrict__ out) {
    const int t = threadIdx.x;
    const int lane = t & 31;
    const int warp = t >> 5;
    const int y = blockIdx.y;
    const int rbase = blockIdx.x * 32 + warp * 4;

    const float4* w40 = (const float4*)(o_w + (size_t)(rbase + 0) * Hdim);
    const float4* w41 = (const float4*)(o_w + (size_t)(rbase + 1) * Hdim);
    const float4* w42 = (const float4*)(o_w + (size_t)(rbase + 2) * Hdim);
    const float4* w43 = (const float4*)(o_w + (size_t)(rbase + 3) * Hdim);

    float acc[4][8];
#pragma unroll
    for (int r = 0; r < 4; r++)
#pragma unroll
        for (int b = 0; b < 8; b++) acc[r][b] = 0.f;

    gemv4x8_pipe((const float4*)g_attn, w40, w41, w42, w43, y, lane, acc);

    if (lane == 0) {
#pragma unroll
        for (int r = 0; r < 4; r++)
#pragma unroll
            for (int b = 0; b < 8; b++)
                atomicAdd(&out[(size_t)b * Hdim + rbase + r], acc[r][b]);
    }
}

// helper: sum qkv partials for (batch b, virtual row vr)
__device__ __forceinline__ float qkv_sum(int b, int vr) {
    float s = 0.f;
#pragma unroll
    for (int yy = 0; yy < NSPLIT; yy++)
        s += g_qkvp[(size_t)(yy * 8 + b) * QKVROWS + vr];
    return s;
}

// ============================================================
// Attention partial (flash-decode split-K) with fused RoPE.
// grid = (16 chunks, 32 rows), 256 threads, dynamic smem.
// K halves streamed via cp.async.128 into a rotate-swizzled
// float4 layout: pos(row,c4) = row*32 + ((c4+row)&31).
//  - staging: warp = one row, lanes = rotated float4 cols (cf-free)
//  - phase1 : thread j reads row j, lanes hit distinct banks (cf-free)
// ============================================================
// smem floats: ks 16384 | q_s 896 | p_s 1792 | knew 128 | vnew 128 | acc2 896
#define SM_KS    0
#define SM_Q     16384
#define SM_P     (16384 + 896)
#define SM_KNEW  (16384 + 896 + 1792)
#define SM_VNEW  (16384 + 896 + 1792 + 128)
#define SM_ACC2  (16384 + 896 + 1792 + 128 + 128)
#define SMEM_ATTN ((16384 + 896 + 1792 + 128 + 128 + 896) * 4)

__global__ __launch_bounds__(256, 2) void attn_partial(
        const float* __restrict__ k_pool,
        const float* __restrict__ v_pool,
        const int* __restrict__ block_table,
        const int* __restrict__ cache_seqlens,
        const float* __restrict__ cos_,
        const float* __restrict__ sin_) {
    const int c = blockIdx.x;
    const int r = blockIdx.y;
    const int seqlen = cache_seqlens[r];
    const int base = c * BSZ;
    if (base >= seqlen) return;

    extern __shared__ float sm[];
    float*  ks     = sm + SM_KS;
    float4* ks4    = (float4*)ks;
    float*  q_s    = sm + SM_Q;
    float*  p_s    = sm + SM_P;
    float*  knew_s = sm + SM_KNEW;
    float*  vnew_s = sm + SM_VNEW;
    float*  acc2_s = sm + SM_ACC2;
    const uint32_t ks_base = (uint32_t)__cvta_generic_to_shared(ks);

    const int nvalid = min(BSZ, seqlen - base);
    const int pos = seqlen - 1;
    const int jpos = pos - base;
    const int b = r >> 2;
    const int kvh = r & 3;
    const int blk = block_table[r * MB + c];
    const float* __restrict__ K = k_pool + (size_t)blk * BSZ * HD;
    const float* __restrict__ V = v_pool + (size_t)blk * BSZ * HD;

    const int t = threadIdx.x;
    const float* cb = cos_ + b * HD;
    const float* sb = sin_ + b * HD;

    // ---- build q (7 heads, rope), k_new (rope), v_new from qkv partials ----
    {
        const int qvbase = kvh * GS * HD;
        for (int i = t; i < GS * 64; i += 256) {
            const int g = i >> 6;
            const int d = i & 63;
            const float cc = cb[d], ss = sb[d];
            const float a  = qkv_sum(b, qvbase + g * HD + d);
            const float b2 = qkv_sum(b, qvbase + g * HD + d + 64);
            q_s[g * HD + d]      = a * cc - b2 * ss;
            q_s[g * HD + d + 64] = b2 * cc + a * ss;
        }
        if (t < 64) {   // k_new rope pairs
            const int vr = 3584 + kvh * HD + t;
            const float cc = cb[t], ss = sb[t];
            const float a  = qkv_sum(b, vr);
            const float b2 = qkv_sum(b, vr + 64);
            knew_s[t]      = a * cc - b2 * ss;
            knew_s[t + 64] = b2 * cc + a * ss;
        } else if (t < 192) {  // v_new plain
            const int d = t - 64;
            vnew_s[d] = qkv_sum(b, 4096 + kvh * HD + d);
        }
    }

    // ---- phase 1: QK scores via cp.async-staged swizzled halves ----
    const int jl = t & 127;
    const int hh = t >> 7;
    const bool valid_tok = (t < nvalid);
    float sc[GS];
#pragma unroll
    for (int g = 0; g < GS; g++) sc[g] = 0.f;

    for (int h = 0; h < 2; h++) {
        const int hbase = h * 128;
        if (hbase >= nvalid) break;
        __syncthreads();   // prev-half compute done / q+knew ready

        // stage 128 rows (64 KB) via cp.async into swizzled layout
        const float4* Ksrc4 = (const float4*)(K + (size_t)hbase * HD);
#pragma unroll
        for (int ii = 0; ii < 16; ii++) {
            const int idx = t + ii * 256;          // 0..4095
            const int row = idx >> 5;
            const int c4  = idx & 31;
            const uint32_t dst = ks_base + (uint32_t)((((row << 5) + ((c4 + row) & 31))) << 4);
            CPA16(dst, Ksrc4 + idx);
        }
        CP_COMMIT();
        CP_WAIT0();
        __syncthreads();   // all threads' copies landed

        // substitute rope'd new-token row (post-landing fixup)
        const int jloc = jpos - hbase;
        if (jloc >= 0 && jloc < 128) {
            if (t < 32)
                ks4[(jloc << 5) + ((t + jloc) & 31)] = ((const float4*)knew_s)[t];
            __syncthreads();
        }

        if (hh == h && valid_tok) {
            const float4* q4 = (const float4*)q_s;
            const int jrow = jl;
#pragma unroll 4
            for (int u = 0; u < 32; u++) {
                const float4 kv = ks4[(jrow << 5) + ((u + jrow) & 31)];
#pragma unroll
                for (int g = 0; g < GS; g++) {
                    const float4 qv = q4[g * 32 + u];
                    sc[g] += kv.x * qv.x + kv.y * qv.y + kv.z * qv.z + kv.w * qv.w;
                }
            }
        }
    }

    // ---- phase 2: softmax, warp per head ----
#pragma unroll
    for (int g = 0; g < GS; g++)
        p_s[g * 256 + t] = valid_tok ? sc[g] * SCALE : NEG_INF;
    __syncthreads();

    const int lane = t & 31, warp = t >> 5;
    const int rc = r * MB + c;
    if (warp < GS) {
        const int g = warp;
        float v[8];
#pragma unroll
        for (int i = 0; i < 8; i++) v[i] = p_s[g * 256 + lane + i * 32];
        float m = v[0];
#pragma unroll
        for (int i = 1; i < 8; i++) m = fmaxf(m, v[i]);
#pragma unroll
        for (int off = 16; off; off >>= 1)
            m = fmaxf(m, __shfl_xor_sync(0xffffffffu, m, off));
        float l = 0.f;
#pragma unroll
        for (int i = 0; i < 8; i++) {
            const float e = __expf(v[i] - m);
            p_s[g * 256 + lane + i * 32] = e;
            l += e;
        }
#pragma unroll
        for (int off = 16; off; off >>= 1)
            l += __shfl_xor_sync(0xffffffffu, l, off);
        if (lane == 0) {
            g_ml[rc * (GS * 2) + g * 2 + 0] = m;
            g_ml[rc * (GS * 2) + g * 2 + 1] = l;
        }
    }
    __syncthreads();

    // ---- phase 3: PV, thread = dim, tokens split across halves.
    //      8 batched independent V loads per iter; p via LDS.128.
    //      p_s is 0 beyond nvalid, so 8-rounded overrun contributes 0.
    const int d = t & 127;
    const int half = t >> 7;
    const int j0 = half * 128;
    float acc[GS];
#pragma unroll
    for (int g = 0; g < GS; g++) acc[g] = 0.f;
    const int jend = min(128, nvalid - j0);
    if (jend > 0) {
        const int jend8 = (jend + 7) & ~7;
        for (int jj = 0; jj < jend8; jj += 8) {
            const int jt = j0 + jj;
            float vv[8];
#pragma unroll
            for (int q = 0; q < 8; q++)
                vv[q] = (jt + q == jpos) ? vnew_s[d] : V[(size_t)(jt + q) * HD + d];
#pragma unroll
            for (int g = 0; g < GS; g++) {
                const float4 pa = *(const float4*)(p_s + g * 256 + jt);
                const float4 pb = *(const float4*)(p_s + g * 256 + jt + 4);
                acc[g] += pa.x * vv[0] + pa.y * vv[1] + pa.z * vv[2] + pa.w * vv[3]
                        + pb.x * vv[4] + pb.y * vv[5] + pb.z * vv[6] + pb.w * vv[7];
            }
        }
    }
    if (half == 1) {
#pragma unroll
        for (int g = 0; g < GS; g++) acc2_s[g * 128 + d] = acc[g];
    }
    __syncthreads();
    if (half == 0) {
        float* outp = g_part + (size_t)rc * (GS * HD);
#pragma unroll
        for (int g = 0; g < GS; g++)
            outp[g * HD + d] = acc[g] + acc2_s[g * 128 + d];
    }
}

// ============================================================
// Combine split-K partials + zero final out for o_gemv atomics.
// grid = (GS, Rr), 128 threads.  224*128 == 28672 == out size.
// ============================================================
__global__ void attn_combine(const int* __restrict__ cache_seqlens,
                             float* __restrict__ out) {
    const int g = blockIdx.x;
    const int r = blockIdx.y;
    const int d = threadIdx.x;

    out[(blockIdx.y * GS + blockIdx.x) * 128 + d] = 0.f;

    const int seqlen = cache_seqlens[r];
    const int nc = (seqlen + BSZ - 1) >> 8;

    float M = NEG_INF;
    for (int c = 0; c < nc; c++)
        M = fmaxf(M, g_ml[(r * MB + c) * (GS * 2) + g * 2]);
    float L = 0.f, acc = 0.f;
    for (int c = 0; c < nc; c++) {
        const int rc = r * MB + c;
        const float m = g_ml[rc * (GS * 2) + g * 2 + 0];
        const float l = g_ml[rc * (GS * 2) + g * 2 + 1];
        const float w = __expf(m - M);
        L += l * w;
        acc += w * g_part[(size_t)rc * (GS * HD) + g * HD + d];
    }
    const int b = r >> 2, kvh = r & 3;
    g_attn[(size_t)b * Hdim + (kvh * GS + g) * HD + d] = acc / L;
}

// ============================================================
extern "C" void kernel_launch(void* const* d_in, const int* in_sizes, int n_in,
                              void* d_out, int out_size) {
    const float* hid  = (const float*)d_in[0];
    const float* cosw = (const float*)d_in[1];
    const float* sinw = (const float*)d_in[2];
    const float* q_w  = (const float*)d_in[3];
    const float* q_b  = (const float*)d_in[4];
    const float* k_w  = (const float*)d_in[5];
    const float* k_b  = (const float*)d_in[6];
    const float* v_w  = (const float*)d_in[7];
    const float* v_b  = (const float*)d_in[8];
    const float* o_w  = (const float*)d_in[9];
    const float* k_pool = (const float*)d_in[10];
    const float* v_pool = (const float*)d_in[11];
    const int* block_table   = (const int*)d_in[12];
    const int* cache_seqlens = (const int*)d_in[13];
    float* out = (float*)d_out;

    cudaFuncSetAttribute(attn_partial, cudaFuncAttributeMaxDynamicSharedMemorySize, SMEM_ATTN);

    // Fused QKV projections: 4608 rows / 32 per block, 7 col-slices
    qkv_gemv<<<dim3(144, NSPLIT), 256>>>(hid, q_w, q_b, k_w, k_b, v_w, v_b);
    // flash-decode partials (rope + qkv-partial reduce fused inside)
    attn_partial<<<dim3(MB, Rr), 256, SMEM_ATTN>>>(k_pool, v_pool, block_table,
                                                   cache_seqlens, cosw, sinw);
    // combine + zero out
    attn_combine<<<dim3(GS, Rr), 128>>>(cache_seqlens, out);
    // O projection: 3584 rows / 32 per block, 7 col-slices, atomic accumulate
    o_gemv<<<dim3(112, NSPLIT), 256>>>(o_w, out);
}

// round 14
// speedup vs baseline: 1.4085x; 1.0546x over previous
#include <cuda_runtime.h>
#include <cuda_bf16.h>
#include <math.h>
#include <stdint.h>

// Problem constants
#define Hdim   3584
#define Bb     8
#define NH     28
#define KVH    4
#define GS     7
#define HD     128
#define MB     16
#define BSZ    256
#define Rr     32          // B*KVH
#define QKVROWS 4608       // 3584 q + 512 k + 512 v
#define SCALE  0.08838834764831845f
#define NEG_INF (-1e30f)
#define NSPLIT 7           // column splits (3584 / 512)

// -------- scratch (device globals, no allocation) --------
__device__ float g_qkvp[NSPLIT * Bb * QKVROWS]; // qkv partials [y][b][vrow]
__device__ float g_part[Rr * MB * GS * HD];     // per-chunk partial PV sums
__device__ float g_ml[Rr * MB * GS * 2];        // per-chunk (m, l)
__device__ float g_attn[Bb * Hdim];             // attention output pre O-proj

// ---- cp.async helpers ----
#define CPA16(dst_u32, src_ptr) \
    asm volatile("cp.async.cg.shared.global [%0], [%1], 16;" :: "r"(dst_u32), "l"(src_ptr))
#define CP_COMMIT() asm volatile("cp.async.commit_group;")
#define CP_WAIT0()  asm volatile("cp.async.wait_group 0;")

// ---- packed f32x2 fma (sm_100+): both lanes are adjacent columns ----
#define FMA2(acc, w, x) \
    asm("fma.rn.f32x2 %0, %1, %2, %0;" : "+l"(acc) : "l"(w), "l"(x))

// ============================================================
// GEMV core: warp = 4 rows x 512-col slice, 8 batches.
// f32x2 packed FMA along the column axis: operand pairs are
// already register-adjacent inside ulonglong2 (=float4) loads,
// so FFMA count halves with zero packing overhead.
// Double-buffered weight prefetch retained.
// ============================================================
__device__ __forceinline__ void gemv4x8_pipe(const ulonglong2* __restrict__ x2,
                                             const ulonglong2* __restrict__ w40,
                                             const ulonglong2* __restrict__ w41,
                                             const ulonglong2* __restrict__ w42,
                                             const ulonglong2* __restrict__ w43,
                                             int y, int lane, float accf[4][8]) {
    unsigned long long acc[4][8];
#pragma unroll
    for (int r = 0; r < 4; r++)
#pragma unroll
        for (int b = 0; b < 8; b++) acc[r][b] = 0ULL;

    const int cb = y * 128 + lane;
    ulonglong2 wc0 = w40[cb];
    ulonglong2 wc1 = w41[cb];
    ulonglong2 wc2 = w42[cb];
    ulonglong2 wc3 = w43[cb];

#pragma unroll
    for (int u = 0; u < 4; u++) {
        ulonglong2 wn0, wn1, wn2, wn3;
        if (u < 3) {
            const int cn = cb + (u + 1) * 32;
            wn0 = w40[cn];
            wn1 = w41[cn];
            wn2 = w42[cn];
            wn3 = w43[cn];
        }
        const int c4 = cb + u * 32;
#pragma unroll
        for (int b = 0; b < 8; b++) {
            const ulonglong2 xv = x2[b * 896 + c4];
            FMA2(acc[0][b], wc0.x, xv.x); FMA2(acc[0][b], wc0.y, xv.y);
            FMA2(acc[1][b], wc1.x, xv.x); FMA2(acc[1][b], wc1.y, xv.y);
            FMA2(acc[2][b], wc2.x, xv.x); FMA2(acc[2][b], wc2.y, xv.y);
            FMA2(acc[3][b], wc3.x, xv.x); FMA2(acc[3][b], wc3.y, xv.y);
        }
        if (u < 3) { wc0 = wn0; wc1 = wn1; wc2 = wn2; wc3 = wn3; }
    }

#pragma unroll
    for (int r = 0; r < 4; r++)
#pragma unroll
        for (int b = 0; b < 8; b++) {
            const unsigned long long a = acc[r][b];
            float s = __uint_as_float((unsigned)(a & 0xffffffffu))
                    + __uint_as_float((unsigned)(a >> 32));
#pragma unroll
            for (int off = 16; off; off >>= 1)
                s += __shfl_xor_sync(0xffffffffu, s, off);
            accf[r][b] = s;
        }
}

// Fused QKV projection. grid (144, 7), 256 threads.
__global__ __launch_bounds__(256, 2) void qkv_gemv(
    const float* __restrict__ hid,
    const float* __restrict__ q_w, const float* __restrict__ q_b,
    const float* __restrict__ k_w, const float* __restrict__ k_b,
    const float* __restrict__ v_w, const float* __restrict__ v_b) {
    const int t = threadIdx.x;
    const int lane = t & 31;
    const int warp = t >> 5;
    const int y = blockIdx.y;
    const int rbase = blockIdx.x * 32 + warp * 4;   // virtual row base

    const float* W; const float* bias; int wrow;
    if (rbase < 3584)      { W = q_w; bias = q_b; wrow = rbase; }
    else if (rbase < 4096) { W = k_w; bias = k_b; wrow = rbase - 3584; }
    else                   { W = v_w; bias = v_b; wrow = rbase - 4096; }

    const ulonglong2* w40 = (const ulonglong2*)(W + (size_t)(wrow + 0) * Hdim);
    const ulonglong2* w41 = (const ulonglong2*)(W + (size_t)(wrow + 1) * Hdim);
    const ulonglong2* w42 = (const ulonglong2*)(W + (size_t)(wrow + 2) * Hdim);
    const ulonglong2* w43 = (const ulonglong2*)(W + (size_t)(wrow + 3) * Hdim);

    float acc[4][8];
    gemv4x8_pipe((const ulonglong2*)hid, w40, w41, w42, w43, y, lane, acc);

    if (lane == 0) {
#pragma unroll
        for (int r = 0; r < 4; r++) {
            const float bv = (y == 0) ? bias[wrow + r] : 0.f;
#pragma unroll
            for (int b = 0; b < 8; b++)
                g_qkvp[(size_t)(y * 8 + b) * QKVROWS + rbase + r] = acc[r][b] + bv;
        }
    }
}

// O projection. grid (112, 7), 256 threads.
// Atomic accumulate into out (zeroed earlier by attn_combine).
__global__ __launch_bounds__(256, 2) void o_gemv(const float* __restrict__ o_w,
                                                 float* __restrict__ out) {
    const int t = threadIdx.x;
    const int lane = t & 31;
    const int warp = t >> 5;
    const int y = blockIdx.y;
    const int rbase = blockIdx.x * 32 + warp * 4;

    const ulonglong2* w40 = (const ulonglong2*)(o_w + (size_t)(rbase + 0) * Hdim);
    const ulonglong2* w41 = (const ulonglong2*)(o_w + (size_t)(rbase + 1) * Hdim);
    const ulonglong2* w42 = (const ulonglong2*)(o_w + (size_t)(rbase + 2) * Hdim);
    const ulonglong2* w43 = (const ulonglong2*)(o_w + (size_t)(rbase + 3) * Hdim);

    float acc[4][8];
    gemv4x8_pipe((const ulonglong2*)g_attn, w40, w41, w42, w43, y, lane, acc);

    if (lane == 0) {
#pragma unroll
        for (int r = 0; r < 4; r++)
#pragma unroll
            for (int b = 0; b < 8; b++)
                atomicAdd(&out[(size_t)b * Hdim + rbase + r], acc[r][b]);
    }
}

// helper: sum qkv partials for (batch b, virtual row vr)
__device__ __forceinline__ float qkv_sum(int b, int vr) {
    float s = 0.f;
#pragma unroll
    for (int yy = 0; yy < NSPLIT; yy++)
        s += g_qkvp[(size_t)(yy * 8 + b) * QKVROWS + vr];
    return s;
}

// ============================================================
// Attention partial (flash-decode split-K) with fused RoPE.
// grid = (16 chunks, 32 rows), 256 threads, dynamic smem.
// K AND V streamed via cp.async.128 into the rotate-swizzled
// ks buffer (V reuses it after phase 1; V0 staged during softmax).
// ============================================================
// smem floats: ks 16384 | q_s 896 | p_s 1792 | knew 128 | vnew 128 | acc2 896
#define SM_KS    0
#define SM_Q     16384
#define SM_P     (16384 + 896)
#define SM_KNEW  (16384 + 896 + 1792)
#define SM_VNEW  (16384 + 896 + 1792 + 128)
#define SM_ACC2  (16384 + 896 + 1792 + 128 + 128)
#define SMEM_ATTN ((16384 + 896 + 1792 + 128 + 128 + 896) * 4)

// stage 128 rows x 128 floats from SRC4 (float4*) into swizzled ks
#define STAGE_KV(SRC4)                                                             \
    { _Pragma("unroll")                                                            \
      for (int ii = 0; ii < 16; ii++) {                                            \
          const int idx = t + ii * 256;                                            \
          const int row_ = idx >> 5;                                               \
          const int c4_  = idx & 31;                                               \
          const uint32_t dst = ks_base +                                           \
              (uint32_t)((((row_ << 5) + ((c4_ + row_) & 31))) << 4);              \
          CPA16(dst, (SRC4) + idx);                                                \
      }                                                                            \
      CP_COMMIT(); }

__device__ __forceinline__ float ks_read_f(const float* ks, int row, int d) {
    const int c4 = d >> 2;
    const int w = (row << 5) + ((c4 + row) & 31);
    return ks[(w << 2) + (d & 3)];
}

__global__ __launch_bounds__(256, 2) void attn_partial(
        const float* __restrict__ k_pool,
        const float* __restrict__ v_pool,
        const int* __restrict__ block_table,
        const int* __restrict__ cache_seqlens,
        const float* __restrict__ cos_,
        const float* __restrict__ sin_) {
    const int c = blockIdx.x;
    const int r = blockIdx.y;
    const int seqlen = cache_seqlens[r];
    const int base = c * BSZ;
    if (base >= seqlen) return;

    extern __shared__ float sm[];
    float*  ks     = sm + SM_KS;
    float4* ks4    = (float4*)ks;
    float*  q_s    = sm + SM_Q;
    float*  p_s    = sm + SM_P;
    float*  knew_s = sm + SM_KNEW;
    float*  vnew_s = sm + SM_VNEW;
    float*  acc2_s = sm + SM_ACC2;
    const uint32_t ks_base = (uint32_t)__cvta_generic_to_shared(ks);

    const int nvalid = min(BSZ, seqlen - base);
    const int pos = seqlen - 1;
    const int jpos = pos - base;      // in [0,256) ONLY for the last chunk
    const int b = r >> 2;
    const int kvh = r & 3;
    const int blk = block_table[r * MB + c];
    const float* __restrict__ K = k_pool + (size_t)blk * BSZ * HD;
    const float* __restrict__ V = v_pool + (size_t)blk * BSZ * HD;

    const int t = threadIdx.x;
    const float* cb = cos_ + b * HD;
    const float* sb = sin_ + b * HD;

    // ---- build q (7 heads, rope), k_new (rope), v_new from qkv partials ----
    {
        const int qvbase = kvh * GS * HD;
        for (int i = t; i < GS * 64; i += 256) {
            const int g = i >> 6;
            const int d = i & 63;
            const float cc = cb[d], ss = sb[d];
            const float a  = qkv_sum(b, qvbase + g * HD + d);
            const float b2 = qkv_sum(b, qvbase + g * HD + d + 64);
            q_s[g * HD + d]      = a * cc - b2 * ss;
            q_s[g * HD + d + 64] = b2 * cc + a * ss;
        }
        if (t < 64) {   // k_new rope pairs
            const int vr = 3584 + kvh * HD + t;
            const float cc = cb[t], ss = sb[t];
            const float a  = qkv_sum(b, vr);
            const float b2 = qkv_sum(b, vr + 64);
            knew_s[t]      = a * cc - b2 * ss;
            knew_s[t + 64] = b2 * cc + a * ss;
        } else if (t < 192) {  // v_new plain
            const int d = t - 64;
            vnew_s[d] = qkv_sum(b, 4096 + kvh * HD + d);
        }
    }

    // ---- phase 1: QK scores via cp.async-staged swizzled halves ----
    const int jl = t & 127;
    const int hh = t >> 7;
    const bool valid_tok = (t < nvalid);
    float sc[GS];
#pragma unroll
    for (int g = 0; g < GS; g++) sc[g] = 0.f;

    for (int h = 0; h < 2; h++) {
        const int hbase = h * 128;
        if (hbase >= nvalid) break;
        __syncthreads();   // prev-half compute done / q+knew ready

        const float4* Ksrc4 = (const float4*)(K + (size_t)hbase * HD);
        STAGE_KV(Ksrc4)
        CP_WAIT0();
        __syncthreads();

        // substitute rope'd new-token row (post-landing fixup)
        const int jloc = jpos - hbase;
        if (jloc >= 0 && jloc < 128) {
            if (t < 32)
                ks4[(jloc << 5) + ((t + jloc) & 31)] = ((const float4*)knew_s)[t];
            __syncthreads();
        }

        if (hh == h && valid_tok) {
            const float4* q4 = (const float4*)q_s;
            const int jrow = jl;
#pragma unroll 4
            for (int u = 0; u < 32; u++) {
                const float4 kv = ks4[(jrow << 5) + ((u + jrow) & 31)];
#pragma unroll
                for (int g = 0; g < GS; g++) {
                    const float4 qv = q4[g * 32 + u];
                    sc[g] += kv.x * qv.x + kv.y * qv.y + kv.z * qv.z + kv.w * qv.w;
                }
            }
        }
    }
    __syncthreads();   // all K reads done; ks free for V

    // ---- stage V half 0 now; it lands while softmax runs ----
    STAGE_KV((const float4*)V)

    // ---- phase 2: softmax, warp per head ----
#pragma unroll
    for (int g = 0; g < GS; g++)
        p_s[g * 256 + t] = valid_tok ? sc[g] * SCALE : NEG_INF;
    __syncthreads();

    const int lane = t & 31, warp = t >> 5;
    const int rc = r * MB + c;
    if (warp < GS) {
        const int g = warp;
        float v[8];
#pragma unroll
        for (int i = 0; i < 8; i++) v[i] = p_s[g * 256 + lane + i * 32];
        float m = v[0];
#pragma unroll
        for (int i = 1; i < 8; i++) m = fmaxf(m, v[i]);
#pragma unroll
        for (int off = 16; off; off >>= 1)
            m = fmaxf(m, __shfl_xor_sync(0xffffffffu, m, off));
        float l = 0.f;
#pragma unroll
        for (int i = 0; i < 8; i++) {
            const float e = __expf(v[i] - m);
            p_s[g * 256 + lane + i * 32] = e;
            l += e;
        }
#pragma unroll
        for (int off = 16; off; off >>= 1)
            l += __shfl_xor_sync(0xffffffffu, l, off);
        if (lane == 0) {
            g_ml[rc * (GS * 2) + g * 2 + 0] = m;
            g_ml[rc * (GS * 2) + g * 2 + 1] = l;
        }
    }
    CP_WAIT0();
    __syncthreads();   // p_s final AND V half 0 landed

    // ---- phase 3: PV from smem V. thread = (d, half); each half
    //      covers 64 tokens of the staged 128-token V half.
    //      p_s is 0 for invalid tokens, so no bounds checks needed.
    const int d = t & 127;
    const int half = t >> 7;
    float acc[GS];
#pragma unroll
    for (int g = 0; g < GS; g++) acc[g] = 0.f;

    // V half 0 fixup (new token row) — only when jpos is in this half
    if (jpos < 128) {
        if (t < 32)
            ks4[(jpos << 5) + ((t + jpos) & 31)] = ((const float4*)vnew_s)[t];
        __syncthreads();
    }
    {
        const int jb = half * 64;
#pragma unroll 4
        for (int jj = 0; jj < 64; jj += 4) {
            const int rl = jb + jj;
            const float v0 = ks_read_f(ks, rl + 0, d);
            const float v1 = ks_read_f(ks, rl + 1, d);
            const float v2 = ks_read_f(ks, rl + 2, d);
            const float v3 = ks_read_f(ks, rl + 3, d);
#pragma unroll
            for (int g = 0; g < GS; g++) {
                const float4 p = *(const float4*)(p_s + g * 256 + rl);
                acc[g] += p.x * v0 + p.y * v1 + p.z * v2 + p.w * v3;
            }
        }
    }
    if (nvalid > 128) {
        __syncthreads();   // all reads of V half 0 done
        STAGE_KV((const float4*)(V + 128 * HD))
        CP_WAIT0();
        __syncthreads();
        // V half 1 fixup — BOTH bounds required: jpos >= 256 for all
        // non-final chunks (this was the R13 illegal-access bug).
        const int jloc = jpos - 128;
        if (jloc >= 0 && jloc < 128) {
            if (t < 32)
                ks4[(jloc << 5) + ((t + jloc) & 31)] = ((const float4*)vnew_s)[t];
            __syncthreads();
        }
        const int jb = half * 64;
#pragma unroll 4
        for (int jj = 0; jj < 64; jj += 4) {
            const int rl = jb + jj;
            const float v0 = ks_read_f(ks, rl + 0, d);
            const float v1 = ks_read_f(ks, rl + 1, d);
            const float v2 = ks_read_f(ks, rl + 2, d);
            const float v3 = ks_read_f(ks, rl + 3, d);
#pragma unroll
            for (int g = 0; g < GS; g++) {
                const float4 p = *(const float4*)(p_s + g * 256 + 128 + rl);
                acc[g] += p.x * v0 + p.y * v1 + p.z * v2 + p.w * v3;
            }
        }
    }

    // combine the two thread-halves
    if (half == 1) {
#pragma unroll
        for (int g = 0; g < GS; g++) acc2_s[g * 128 + d] = acc[g];
    }
    __syncthreads();
    if (half == 0) {
        float* outp = g_part + (size_t)rc * (GS * HD);
#pragma unroll
        for (int g = 0; g < GS; g++)
            outp[g * HD + d] = acc[g] + acc2_s[g * 128 + d];
    }
}

// ============================================================
// Combine split-K partials + zero final out for o_gemv atomics.
// grid = (GS, Rr), 128 threads.  224*128 == 28672 == out size.
// ============================================================
__global__ void attn_combine(const int* __restrict__ cache_seqlens,
                             float* __restrict__ out) {
    const int g = blockIdx.x;
    const int r = blockIdx.y;
    const int d = threadIdx.x;

    out[(blockIdx.y * GS + blockIdx.x) * 128 + d] = 0.f;

    const int seqlen = cache_seqlens[r];
    const int nc = (seqlen + BSZ - 1) >> 8;

    float M = NEG_INF;
    for (int c = 0; c < nc; c++)
        M = fmaxf(M, g_ml[(r * MB + c) * (GS * 2) + g * 2]);
    float L = 0.f, acc = 0.f;
    for (int c = 0; c < nc; c++) {
        const int rc = r * MB + c;
        const float m = g_ml[rc * (GS * 2) + g * 2 + 0];
        const float l = g_ml[rc * (GS * 2) + g * 2 + 1];
        const float w = __expf(m - M);
        L += l * w;
        acc += w * g_part[(size_t)rc * (GS * HD) + g * HD + d];
    }
    const int b = r >> 2, kvh = r & 3;
    g_attn[(size_t)b * Hdim + (kvh * GS + g) * HD + d] = acc / L;
}

// ============================================================
extern "C" void kernel_launch(void* const* d_in, const int* in_sizes, int n_in,
                              void* d_out, int out_size) {
    const float* hid  = (const float*)d_in[0];
    const float* cosw = (const float*)d_in[1];
    const float* sinw = (const float*)d_in[2];
    const float* q_w  = (const float*)d_in[3];
    const float* q_b  = (const float*)d_in[4];
    const float* k_w  = (const float*)d_in[5];
    const float* k_b  = (const float*)d_in[6];
    const float* v_w  = (const float*)d_in[7];
    const float* v_b  = (const float*)d_in[8];
    const float* o_w  = (const float*)d_in[9];
    const float* k_pool = (const float*)d_in[10];
    const float* v_pool = (const float*)d_in[11];
    const int* block_table   = (const int*)d_in[12];
    const int* cache_seqlens = (const int*)d_in[13];
    float* out = (float*)d_out;

    cudaFuncSetAttribute(attn_partial, cudaFuncAttributeMaxDynamicSharedMemorySize, SMEM_ATTN);

    // Fused QKV projections: 4608 rows / 32 per block, 7 col-slices
    qkv_gemv<<<dim3(144, NSPLIT), 256>>>(hid, q_w, q_b, k_w, k_b, v_w, v_b);
    // flash-decode partials (rope + qkv-partial reduce fused inside)
    attn_partial<<<dim3(MB, Rr), 256, SMEM_ATTN>>>(k_pool, v_pool, block_table,
                                                   cache_seqlens, cosw, sinw);
    // combine + zero out
    attn_combine<<<dim3(GS, Rr), 128>>>(cache_seqlens, out);
    // O projection: 3584 rows / 32 per block, 7 col-slices, atomic accumulate
    o_gemv<<<dim3(112, NSPLIT), 256>>>(o_w, out);
}